// round 9
// baseline (speedup 1.0000x reference)
#include <cuda_runtime.h>
#include <math.h>

#define H    2048
#define TPB  256
#define NWARP (TPB / 32)
#define L    3

// Inter-layer hidden state: [0] = h1 (layer0 out), [1] = h2 (layer1 out)
__device__ __align__(16) float g_hbuf[2][H];
// Precomputed P[l-1][gate][j] = (Wh_l @ h0_l)[gate*H+j] + bi + bh, layers 1,2
__device__ __align__(16) float g_P[2][4][H];

__device__ __forceinline__ float dot4(float4 w, float4 v) {
    return w.x * v.x + w.y * v.y + w.z * v.z + w.w * v.w;
}
__device__ __forceinline__ float sigmoidf_(float v) {
    return 1.0f / (1.0f + __expf(-v));
}
__device__ __forceinline__ void l2_prefetch(const void* p) {
    asm volatile("prefetch.global.L2 [%0];" :: "l"(p));
}

// ---------------------------------------------------------------------------
// K1 (R5-verbatim body, measured 44.06us @ 78% DRAM): grid = 6144.
//   blocks [0,2048):     full layer-0 cell -> g_hbuf[0]
//   blocks [2048,4096):  P for layer 1     -> g_P[0]
//   blocks [4096,6144):  P for layer 2     -> g_P[1]
// Each block triggers programmatic completion after its last write so the
// PDL secondary's cudaGridDependencySynchronize() releases ASAP.
// ---------------------------------------------------------------------------
__global__ void __launch_bounds__(TPB) lstm_k1(
    const float* __restrict__ x,
    const float* __restrict__ W_ih,
    const float* __restrict__ W_hh,
    const float* __restrict__ b_ih,
    const float* __restrict__ b_hh,
    const float* __restrict__ h0,
    const float* __restrict__ c0)
{
    const int b    = blockIdx.x;
    const int t    = threadIdx.x;
    const int warp = t >> 5;
    const int lane = t & 31;

    __shared__ float s[4][NWARP];

    if (b < H) {
        const int j = b;
        const float4* __restrict__ x4 = (const float4*)x;
        const float4* __restrict__ h4 = (const float4*)h0;

        const float4* __restrict__ wi0 = (const float4*)(W_ih + (size_t)(0 * H + j) * H);
        const float4* __restrict__ wi1 = (const float4*)(W_ih + (size_t)(1 * H + j) * H);
        const float4* __restrict__ wi2 = (const float4*)(W_ih + (size_t)(2 * H + j) * H);
        const float4* __restrict__ wi3 = (const float4*)(W_ih + (size_t)(3 * H + j) * H);
        const float4* __restrict__ wh0 = (const float4*)(W_hh + (size_t)(0 * H + j) * H);
        const float4* __restrict__ wh1 = (const float4*)(W_hh + (size_t)(1 * H + j) * H);
        const float4* __restrict__ wh2 = (const float4*)(W_hh + (size_t)(2 * H + j) * H);
        const float4* __restrict__ wh3 = (const float4*)(W_hh + (size_t)(3 * H + j) * H);

        float a0 = 0.f, a1 = 0.f, a2 = 0.f, a3 = 0.f;
        #pragma unroll
        for (int k = t; k < H / 4; k += TPB) {
            float4 xv = x4[k];
            float4 hv = h4[k];
            a0 += dot4(wi0[k], xv);
            a1 += dot4(wi1[k], xv);
            a2 += dot4(wi2[k], xv);
            a3 += dot4(wi3[k], xv);
            a0 += dot4(wh0[k], hv);
            a1 += dot4(wh1[k], hv);
            a2 += dot4(wh2[k], hv);
            a3 += dot4(wh3[k], hv);
        }
        #pragma unroll
        for (int off = 16; off > 0; off >>= 1) {
            a0 += __shfl_xor_sync(0xffffffffu, a0, off);
            a1 += __shfl_xor_sync(0xffffffffu, a1, off);
            a2 += __shfl_xor_sync(0xffffffffu, a2, off);
            a3 += __shfl_xor_sync(0xffffffffu, a3, off);
        }
        if (lane == 0) { s[0][warp] = a0; s[1][warp] = a1; s[2][warp] = a2; s[3][warp] = a3; }
        __syncthreads();
        if (t == 0) {
            float gi = 0.f, gf = 0.f, gg = 0.f, go = 0.f;
            #pragma unroll
            for (int w = 0; w < NWARP; w++) {
                gi += s[0][w]; gf += s[1][w]; gg += s[2][w]; go += s[3][w];
            }
            gi += b_ih[0 * H + j] + b_hh[0 * H + j];
            gf += b_ih[1 * H + j] + b_hh[1 * H + j];
            gg += b_ih[2 * H + j] + b_hh[2 * H + j];
            go += b_ih[3 * H + j] + b_hh[3 * H + j];
            float iv = sigmoidf_(gi);
            float fv = sigmoidf_(gf);
            float gv = tanhf(gg);
            float ov = sigmoidf_(go);
            float c_new = fv * c0[j] + iv * gv;
            g_hbuf[0][j] = ov * tanhf(c_new);
        }
    } else {
        const int bb = b - H;
        const int l  = 1 + (bb >> 11);
        const int j  = bb & (H - 1);
        const float* Wh = W_hh + (size_t)l * 4 * H * H;
        const float* bi = b_ih + l * 4 * H;
        const float* bh = b_hh + l * 4 * H;
        const float4* __restrict__ h4 = (const float4*)(h0 + l * H);

        const float4* __restrict__ r0 = (const float4*)(Wh + (size_t)(0 * H + j) * H);
        const float4* __restrict__ r1 = (const float4*)(Wh + (size_t)(1 * H + j) * H);
        const float4* __restrict__ r2 = (const float4*)(Wh + (size_t)(2 * H + j) * H);
        const float4* __restrict__ r3 = (const float4*)(Wh + (size_t)(3 * H + j) * H);

        float a0 = 0.f, a1 = 0.f, a2 = 0.f, a3 = 0.f;
        #pragma unroll
        for (int k = t; k < H / 4; k += TPB) {
            float4 hv = h4[k];
            a0 += dot4(r0[k], hv);
            a1 += dot4(r1[k], hv);
            a2 += dot4(r2[k], hv);
            a3 += dot4(r3[k], hv);
        }
        #pragma unroll
        for (int off = 16; off > 0; off >>= 1) {
            a0 += __shfl_xor_sync(0xffffffffu, a0, off);
            a1 += __shfl_xor_sync(0xffffffffu, a1, off);
            a2 += __shfl_xor_sync(0xffffffffu, a2, off);
            a3 += __shfl_xor_sync(0xffffffffu, a3, off);
        }
        if (lane == 0) { s[0][warp] = a0; s[1][warp] = a1; s[2][warp] = a2; s[3][warp] = a3; }
        __syncthreads();
        if (t == 0) {
            float p0 = 0.f, p1 = 0.f, p2 = 0.f, p3 = 0.f;
            #pragma unroll
            for (int w = 0; w < NWARP; w++) {
                p0 += s[0][w]; p1 += s[1][w]; p2 += s[2][w]; p3 += s[3][w];
            }
            g_P[l - 1][0][j] = p0 + bi[0 * H + j] + bh[0 * H + j];
            g_P[l - 1][1][j] = p1 + bi[1 * H + j] + bh[1 * H + j];
            g_P[l - 1][2][j] = p2 + bi[2 * H + j] + bh[2 * H + j];
            g_P[l - 1][3][j] = p3 + bi[3 * H + j] + bh[3 * H + j];
        }
    }
    cudaTriggerProgrammaticLaunchCompletion();
}

// ---------------------------------------------------------------------------
// K2/K3 with PDL: blocks may start during the predecessor's drain. Pre-sync
// they prefetch this block's 64KB of weight rows into L2 (input-independent),
// then cudaGridDependencySynchronize() (waits for predecessor's triggers =
// all its writes), then the proven Wi body runs against a warm L2.
// ---------------------------------------------------------------------------
__global__ void __launch_bounds__(TPB, 8) lstm_wi_pdl(
    const float* __restrict__ Wi,    // [4H, H] layer l
    const float* __restrict__ xin,   // [H] = h of previous layer
    const float* __restrict__ cin,   // [H] = c0[l]
    const float* __restrict__ P,     // [4][H]
    float* __restrict__ hout)        // [H]
{
    const int j    = blockIdx.x;
    const int t    = threadIdx.x;
    const int warp = t >> 5;
    const int lane = t & 31;

    const float4* __restrict__ r0 = (const float4*)(Wi + (size_t)(0 * H + j) * H);
    const float4* __restrict__ r1 = (const float4*)(Wi + (size_t)(1 * H + j) * H);
    const float4* __restrict__ r2 = (const float4*)(Wi + (size_t)(2 * H + j) * H);
    const float4* __restrict__ r3 = (const float4*)(Wi + (size_t)(3 * H + j) * H);

    // Pre-sync: prefetch all 4 weight rows (4 x 8KB = 256 x 128B lines) to L2.
    // Thread t covers line t: rows interleaved so threads spread across rows.
    {
        const char* rows[4] = {(const char*)r0, (const char*)r1,
                               (const char*)r2, (const char*)r3};
        l2_prefetch(rows[t >> 6] + (size_t)(t & 63) * 128);
    }

    // Wait for predecessor kernel's writes (xin) to be visible.
    cudaGridDependencySynchronize();

    const float4* __restrict__ x4 = (const float4*)xin;

    float a0 = 0.f, a1 = 0.f, a2 = 0.f, a3 = 0.f;
    #pragma unroll
    for (int k = t; k < H / 4; k += TPB) {
        float4 xv = x4[k];
        a0 += dot4(r0[k], xv);
        a1 += dot4(r1[k], xv);
        a2 += dot4(r2[k], xv);
        a3 += dot4(r3[k], xv);
    }
    #pragma unroll
    for (int off = 16; off > 0; off >>= 1) {
        a0 += __shfl_xor_sync(0xffffffffu, a0, off);
        a1 += __shfl_xor_sync(0xffffffffu, a1, off);
        a2 += __shfl_xor_sync(0xffffffffu, a2, off);
        a3 += __shfl_xor_sync(0xffffffffu, a3, off);
    }
    __shared__ float s[4][NWARP];
    if (lane == 0) { s[0][warp] = a0; s[1][warp] = a1; s[2][warp] = a2; s[3][warp] = a3; }
    __syncthreads();
    if (t == 0) {
        float gi = 0.f, gf = 0.f, gg = 0.f, go = 0.f;
        #pragma unroll
        for (int w = 0; w < NWARP; w++) {
            gi += s[0][w]; gf += s[1][w]; gg += s[2][w]; go += s[3][w];
        }
        gi += P[0 * H + j];
        gf += P[1 * H + j];
        gg += P[2 * H + j];
        go += P[3 * H + j];
        float iv = sigmoidf_(gi);
        float fv = sigmoidf_(gf);
        float gv = tanhf(gg);
        float ov = sigmoidf_(go);
        float c_new = fv * cin[j] + iv * gv;
        hout[j] = ov * tanhf(c_new);
    }
    cudaTriggerProgrammaticLaunchCompletion();
}

extern "C" void kernel_launch(void* const* d_in, const int* in_sizes, int n_in,
                              void* d_out, int out_size) {
    (void)in_sizes; (void)n_in; (void)out_size;
    const float* x    = (const float*)d_in[0];
    const float* W_ih = (const float*)d_in[1];
    const float* W_hh = (const float*)d_in[2];
    const float* b_ih = (const float*)d_in[3];
    const float* b_hh = (const float*)d_in[4];
    const float* h0   = (const float*)d_in[5];
    const float* c0   = (const float*)d_in[6];
    float* out = (float*)d_out;

    float* hbuf;
    cudaGetSymbolAddress((void**)&hbuf, g_hbuf);
    float* P;
    cudaGetSymbolAddress((void**)&P, g_P);

    const size_t Wstride = (size_t)4 * H * H;

    // K1: all input-parallel work (268 MB, 6.92 near-full waves).
    lstm_k1<<<3 * H, TPB>>>(x, W_ih, W_hh, b_ih, b_hh, h0, c0);

    // K2/K3 launched with programmatic stream serialization: their blocks may
    // begin (prefetching weights) while the predecessor drains; data safety is
    // provided by cudaGridDependencySynchronize() inside the kernel.
    cudaLaunchAttribute attrs[1];
    attrs[0].id = cudaLaunchAttributeProgrammaticStreamSerialization;
    attrs[0].val.programmaticStreamSerializationAllowed = 1;

    {
        cudaLaunchConfig_t cfg = {};
        cfg.gridDim  = dim3(H);
        cfg.blockDim = dim3(TPB);
        cfg.dynamicSmemBytes = 0;
        cfg.stream   = 0;
        cfg.attrs    = attrs;
        cfg.numAttrs = 1;
        // K2: layer 1 = Wi_1 @ h1 + P_1 -> h2
        cudaLaunchKernelEx(&cfg, lstm_wi_pdl,
                           (const float*)(W_ih + Wstride), (const float*)hbuf,
                           (const float*)(c0 + H), (const float*)P,
                           (float*)(hbuf + H));
        // K3: layer 2 = Wi_2 @ h2 + P_2 -> out
        cudaLaunchKernelEx(&cfg, lstm_wi_pdl,
                           (const float*)(W_ih + 2 * Wstride), (const float*)(hbuf + H),
                           (const float*)(c0 + 2 * H), (const float*)(P + 4 * H),
                           (float*)out);
    }
}

// round 11
// speedup vs baseline: 1.0678x; 1.0678x over previous
#include <cuda_runtime.h>
#include <math.h>

#define H    2048
#define TPB  256
#define NWARP (TPB / 32)
#define L    3

// Inter-layer hidden state
__device__ __align__(16) float g_hbuf[2][H];
// Precomputed P[l-1][gate][j] = (Wh_l @ h0_l)[gate*H+j] + bi + bh, layers 1,2
__device__ __align__(16) float g_P[2][4][H];

__device__ __forceinline__ float dot4(float4 w, float4 v) {
    return w.x * v.x + w.y * v.y + w.z * v.z + w.w * v.w;
}
__device__ __forceinline__ float sigmoidf_(float v) {
    return 1.0f / (1.0f + __expf(-v));
}
__device__ __forceinline__ float4 ldcs4(const float4* p) {
    return __ldcs(p);
}

// ---------------------------------------------------------------------------
// K1 (VERBATIM R5, measured 44.06us @ 78% DRAM): grid = 6144.
//   blocks [0,2048):     full layer-0 cell -> g_hbuf[0]
//   blocks [2048,4096):  P for layer 1     -> g_P[0]
//   blocks [4096,6144):  P for layer 2     -> g_P[1]
// ---------------------------------------------------------------------------
__global__ void __launch_bounds__(TPB) lstm_k1(
    const float* __restrict__ x,
    const float* __restrict__ W_ih,
    const float* __restrict__ W_hh,
    const float* __restrict__ b_ih,
    const float* __restrict__ b_hh,
    const float* __restrict__ h0,
    const float* __restrict__ c0)
{
    const int b    = blockIdx.x;
    const int t    = threadIdx.x;
    const int warp = t >> 5;
    const int lane = t & 31;

    __shared__ float s[4][NWARP];

    if (b < H) {
        const int j = b;
        const float4* __restrict__ x4 = (const float4*)x;
        const float4* __restrict__ h4 = (const float4*)h0;

        const float4* __restrict__ wi0 = (const float4*)(W_ih + (size_t)(0 * H + j) * H);
        const float4* __restrict__ wi1 = (const float4*)(W_ih + (size_t)(1 * H + j) * H);
        const float4* __restrict__ wi2 = (const float4*)(W_ih + (size_t)(2 * H + j) * H);
        const float4* __restrict__ wi3 = (const float4*)(W_ih + (size_t)(3 * H + j) * H);
        const float4* __restrict__ wh0 = (const float4*)(W_hh + (size_t)(0 * H + j) * H);
        const float4* __restrict__ wh1 = (const float4*)(W_hh + (size_t)(1 * H + j) * H);
        const float4* __restrict__ wh2 = (const float4*)(W_hh + (size_t)(2 * H + j) * H);
        const float4* __restrict__ wh3 = (const float4*)(W_hh + (size_t)(3 * H + j) * H);

        float a0 = 0.f, a1 = 0.f, a2 = 0.f, a3 = 0.f;
        #pragma unroll
        for (int k = t; k < H / 4; k += TPB) {
            float4 xv = x4[k];
            float4 hv = h4[k];
            a0 += dot4(wi0[k], xv);
            a1 += dot4(wi1[k], xv);
            a2 += dot4(wi2[k], xv);
            a3 += dot4(wi3[k], xv);
            a0 += dot4(wh0[k], hv);
            a1 += dot4(wh1[k], hv);
            a2 += dot4(wh2[k], hv);
            a3 += dot4(wh3[k], hv);
        }
        #pragma unroll
        for (int off = 16; off > 0; off >>= 1) {
            a0 += __shfl_xor_sync(0xffffffffu, a0, off);
            a1 += __shfl_xor_sync(0xffffffffu, a1, off);
            a2 += __shfl_xor_sync(0xffffffffu, a2, off);
            a3 += __shfl_xor_sync(0xffffffffu, a3, off);
        }
        if (lane == 0) { s[0][warp] = a0; s[1][warp] = a1; s[2][warp] = a2; s[3][warp] = a3; }
        __syncthreads();
        if (t == 0) {
            float gi = 0.f, gf = 0.f, gg = 0.f, go = 0.f;
            #pragma unroll
            for (int w = 0; w < NWARP; w++) {
                gi += s[0][w]; gf += s[1][w]; gg += s[2][w]; go += s[3][w];
            }
            gi += b_ih[0 * H + j] + b_hh[0 * H + j];
            gf += b_ih[1 * H + j] + b_hh[1 * H + j];
            gg += b_ih[2 * H + j] + b_hh[2 * H + j];
            go += b_ih[3 * H + j] + b_hh[3 * H + j];
            float iv = sigmoidf_(gi);
            float fv = sigmoidf_(gf);
            float gv = tanhf(gg);
            float ov = sigmoidf_(go);
            float c_new = fv * c0[j] + iv * gv;
            g_hbuf[0][j] = ov * tanhf(c_new);
        }
    } else {
        const int bb = b - H;
        const int l  = 1 + (bb >> 11);
        const int j  = bb & (H - 1);
        const float* Wh = W_hh + (size_t)l * 4 * H * H;
        const float* bi = b_ih + l * 4 * H;
        const float* bh = b_hh + l * 4 * H;
        const float4* __restrict__ h4 = (const float4*)(h0 + l * H);

        const float4* __restrict__ r0 = (const float4*)(Wh + (size_t)(0 * H + j) * H);
        const float4* __restrict__ r1 = (const float4*)(Wh + (size_t)(1 * H + j) * H);
        const float4* __restrict__ r2 = (const float4*)(Wh + (size_t)(2 * H + j) * H);
        const float4* __restrict__ r3 = (const float4*)(Wh + (size_t)(3 * H + j) * H);

        float a0 = 0.f, a1 = 0.f, a2 = 0.f, a3 = 0.f;
        #pragma unroll
        for (int k = t; k < H / 4; k += TPB) {
            float4 hv = h4[k];
            a0 += dot4(r0[k], hv);
            a1 += dot4(r1[k], hv);
            a2 += dot4(r2[k], hv);
            a3 += dot4(r3[k], hv);
        }
        #pragma unroll
        for (int off = 16; off > 0; off >>= 1) {
            a0 += __shfl_xor_sync(0xffffffffu, a0, off);
            a1 += __shfl_xor_sync(0xffffffffu, a1, off);
            a2 += __shfl_xor_sync(0xffffffffu, a2, off);
            a3 += __shfl_xor_sync(0xffffffffu, a3, off);
        }
        if (lane == 0) { s[0][warp] = a0; s[1][warp] = a1; s[2][warp] = a2; s[3][warp] = a3; }
        __syncthreads();
        if (t == 0) {
            float p0 = 0.f, p1 = 0.f, p2 = 0.f, p3 = 0.f;
            #pragma unroll
            for (int w = 0; w < NWARP; w++) {
                p0 += s[0][w]; p1 += s[1][w]; p2 += s[2][w]; p3 += s[3][w];
            }
            g_P[l - 1][0][j] = p0 + bi[0 * H + j] + bh[0 * H + j];
            g_P[l - 1][1][j] = p1 + bi[1 * H + j] + bh[1 * H + j];
            g_P[l - 1][2][j] = p2 + bi[2 * H + j] + bh[2 * H + j];
            g_P[l - 1][3][j] = p3 + bi[3 * H + j] + bh[3 * H + j];
        }
    }
}

// ---------------------------------------------------------------------------
// K2/K3: Wi_l @ xin + P_l + epilogue. One block per j, 4 rows.
// Changes vs R5: no occupancy cap (regs free to ~40, 6 blocks/SM like K1),
// all 8 weight loads manually front-batched (guaranteed MLP=8) and issued
// with __ldcs (evict-first streaming; weights are touched exactly once).
// ---------------------------------------------------------------------------
__global__ void __launch_bounds__(TPB) lstm_wi_kernel(
    const float* __restrict__ Wi,    // [4H, H] layer l
    const float* __restrict__ xin,   // [H] = h of previous layer
    const float* __restrict__ cin,   // [H] = c0[l]
    const float* __restrict__ P,     // [4][H]
    float* __restrict__ hout)        // [H]
{
    const int j    = blockIdx.x;
    const int t    = threadIdx.x;
    const int warp = t >> 5;
    const int lane = t & 31;

    const float4* __restrict__ x4 = (const float4*)xin;
    const float4* __restrict__ r0 = (const float4*)(Wi + (size_t)(0 * H + j) * H);
    const float4* __restrict__ r1 = (const float4*)(Wi + (size_t)(1 * H + j) * H);
    const float4* __restrict__ r2 = (const float4*)(Wi + (size_t)(2 * H + j) * H);
    const float4* __restrict__ r3 = (const float4*)(Wi + (size_t)(3 * H + j) * H);

    // Front-batch all 8 weight loads (4 rows x 2 chunks) before any FMA.
    const int kA = t;
    const int kB = t + TPB;
    float4 w0A = ldcs4(&r0[kA]);
    float4 w1A = ldcs4(&r1[kA]);
    float4 w2A = ldcs4(&r2[kA]);
    float4 w3A = ldcs4(&r3[kA]);
    float4 w0B = ldcs4(&r0[kB]);
    float4 w1B = ldcs4(&r1[kB]);
    float4 w2B = ldcs4(&r2[kB]);
    float4 w3B = ldcs4(&r3[kB]);
    float4 xvA = x4[kA];
    float4 xvB = x4[kB];

    float a0 = dot4(w0A, xvA) + dot4(w0B, xvB);
    float a1 = dot4(w1A, xvA) + dot4(w1B, xvB);
    float a2 = dot4(w2A, xvA) + dot4(w2B, xvB);
    float a3 = dot4(w3A, xvA) + dot4(w3B, xvB);

    #pragma unroll
    for (int off = 16; off > 0; off >>= 1) {
        a0 += __shfl_xor_sync(0xffffffffu, a0, off);
        a1 += __shfl_xor_sync(0xffffffffu, a1, off);
        a2 += __shfl_xor_sync(0xffffffffu, a2, off);
        a3 += __shfl_xor_sync(0xffffffffu, a3, off);
    }
    __shared__ float s[4][NWARP];
    if (lane == 0) { s[0][warp] = a0; s[1][warp] = a1; s[2][warp] = a2; s[3][warp] = a3; }
    __syncthreads();
    if (t == 0) {
        float gi = 0.f, gf = 0.f, gg = 0.f, go = 0.f;
        #pragma unroll
        for (int w = 0; w < NWARP; w++) {
            gi += s[0][w]; gf += s[1][w]; gg += s[2][w]; go += s[3][w];
        }
        gi += P[0 * H + j];
        gf += P[1 * H + j];
        gg += P[2 * H + j];
        go += P[3 * H + j];
        float iv = sigmoidf_(gi);
        float fv = sigmoidf_(gf);
        float gv = tanhf(gg);
        float ov = sigmoidf_(go);
        float c_new = fv * cin[j] + iv * gv;
        hout[j] = ov * tanhf(c_new);
    }
}

extern "C" void kernel_launch(void* const* d_in, const int* in_sizes, int n_in,
                              void* d_out, int out_size) {
    (void)in_sizes; (void)n_in; (void)out_size;
    const float* x    = (const float*)d_in[0];
    const float* W_ih = (const float*)d_in[1];
    const float* W_hh = (const float*)d_in[2];
    const float* b_ih = (const float*)d_in[3];
    const float* b_hh = (const float*)d_in[4];
    const float* h0   = (const float*)d_in[5];
    const float* c0   = (const float*)d_in[6];
    float* out = (float*)d_out;

    float* hbuf;
    cudaGetSymbolAddress((void**)&hbuf, g_hbuf);
    float* P;
    cudaGetSymbolAddress((void**)&P, g_P);

    const size_t Wstride = (size_t)4 * H * H;

    // K1: all input-parallel work (268 MB, 6.92 near-full waves)
    lstm_k1<<<3 * H, TPB>>>(x, W_ih, W_hh, b_ih, b_hh, h0, c0);
    // K2: layer 1 = Wi_1 @ h1 + P_1 -> h2
    lstm_wi_kernel<<<H, TPB>>>(W_ih + Wstride, hbuf, c0 + H,
                               P, hbuf + H);
    // K3: layer 2 = Wi_2 @ h2 + P_2 -> out
    lstm_wi_kernel<<<H, TPB>>>(W_ih + 2 * Wstride, hbuf + H, c0 + 2 * H,
                               P + 4 * H, out);
}

// round 13
// speedup vs baseline: 1.2049x; 1.1284x over previous
#include <cuda_runtime.h>
#include <math.h>

#define H    2048
#define TPB  256
#define NWARP (TPB / 32)
#define L    3

// Inter-layer hidden state
__device__ __align__(16) float g_hbuf[2][H];
// Precomputed P[l-1][gate][j] = (Wh_l @ h0_l)[gate*H+j] + bi + bh, layers 1,2
__device__ __align__(16) float g_P[2][4][H];

__device__ __forceinline__ float dot4(float4 w, float4 v) {
    return w.x * v.x + w.y * v.y + w.z * v.z + w.w * v.w;
}
__device__ __forceinline__ float sigmoidf_(float v) {
    return 1.0f / (1.0f + __expf(-v));
}
// Streaming weight load: evict-first so it never displaces the resident set.
__device__ __forceinline__ float4 ld_stream(const float4* p) {
    return __ldcs(p);
}
// Persistent 32-byte weight load: L2::evict_last (sm_103a requires .v4.b64
// width for this modifier). Loads 8 consecutive floats.
__device__ __forceinline__ void ld_keep8(const float* p, float4& a, float4& b) {
    unsigned long long r0, r1, r2, r3;
    asm volatile("ld.global.nc.L2::evict_last.v4.b64 {%0,%1,%2,%3}, [%4];"
                 : "=l"(r0), "=l"(r1), "=l"(r2), "=l"(r3)
                 : "l"(p));
    a.x = __uint_as_float((unsigned)(r0));
    a.y = __uint_as_float((unsigned)(r0 >> 32));
    a.z = __uint_as_float((unsigned)(r1));
    a.w = __uint_as_float((unsigned)(r1 >> 32));
    b.x = __uint_as_float((unsigned)(r2));
    b.y = __uint_as_float((unsigned)(r2 >> 32));
    b.z = __uint_as_float((unsigned)(r3));
    b.w = __uint_as_float((unsigned)(r3 >> 32));
}

// ---------------------------------------------------------------------------
// K1 (R5 structure, weights evict-first streamed): grid = 6144.
//   blocks [0,2048):     full layer-0 cell -> g_hbuf[0]
//   blocks [2048,4096):  P for layer 1     -> g_P[0]
//   blocks [4096,6144):  P for layer 2     -> g_P[1]
// ---------------------------------------------------------------------------
__global__ void __launch_bounds__(TPB) lstm_k1(
    const float* __restrict__ x,
    const float* __restrict__ W_ih,
    const float* __restrict__ W_hh,
    const float* __restrict__ b_ih,
    const float* __restrict__ b_hh,
    const float* __restrict__ h0,
    const float* __restrict__ c0)
{
    const int b    = blockIdx.x;
    const int t    = threadIdx.x;
    const int warp = t >> 5;
    const int lane = t & 31;

    __shared__ float s[4][NWARP];

    if (b < H) {
        const int j = b;
        const float4* __restrict__ x4 = (const float4*)x;
        const float4* __restrict__ h4 = (const float4*)h0;

        const float4* __restrict__ wi0 = (const float4*)(W_ih + (size_t)(0 * H + j) * H);
        const float4* __restrict__ wi1 = (const float4*)(W_ih + (size_t)(1 * H + j) * H);
        const float4* __restrict__ wi2 = (const float4*)(W_ih + (size_t)(2 * H + j) * H);
        const float4* __restrict__ wi3 = (const float4*)(W_ih + (size_t)(3 * H + j) * H);
        const float4* __restrict__ wh0 = (const float4*)(W_hh + (size_t)(0 * H + j) * H);
        const float4* __restrict__ wh1 = (const float4*)(W_hh + (size_t)(1 * H + j) * H);
        const float4* __restrict__ wh2 = (const float4*)(W_hh + (size_t)(2 * H + j) * H);
        const float4* __restrict__ wh3 = (const float4*)(W_hh + (size_t)(3 * H + j) * H);

        float a0 = 0.f, a1 = 0.f, a2 = 0.f, a3 = 0.f;
        #pragma unroll
        for (int k = t; k < H / 4; k += TPB) {
            float4 xv = x4[k];
            float4 hv = h4[k];
            a0 += dot4(ld_stream(&wi0[k]), xv);
            a1 += dot4(ld_stream(&wi1[k]), xv);
            a2 += dot4(ld_stream(&wi2[k]), xv);
            a3 += dot4(ld_stream(&wi3[k]), xv);
            a0 += dot4(ld_stream(&wh0[k]), hv);
            a1 += dot4(ld_stream(&wh1[k]), hv);
            a2 += dot4(ld_stream(&wh2[k]), hv);
            a3 += dot4(ld_stream(&wh3[k]), hv);
        }
        #pragma unroll
        for (int off = 16; off > 0; off >>= 1) {
            a0 += __shfl_xor_sync(0xffffffffu, a0, off);
            a1 += __shfl_xor_sync(0xffffffffu, a1, off);
            a2 += __shfl_xor_sync(0xffffffffu, a2, off);
            a3 += __shfl_xor_sync(0xffffffffu, a3, off);
        }
        if (lane == 0) { s[0][warp] = a0; s[1][warp] = a1; s[2][warp] = a2; s[3][warp] = a3; }
        __syncthreads();
        if (t == 0) {
            float gi = 0.f, gf = 0.f, gg = 0.f, go = 0.f;
            #pragma unroll
            for (int w = 0; w < NWARP; w++) {
                gi += s[0][w]; gf += s[1][w]; gg += s[2][w]; go += s[3][w];
            }
            gi += b_ih[0 * H + j] + b_hh[0 * H + j];
            gf += b_ih[1 * H + j] + b_hh[1 * H + j];
            gg += b_ih[2 * H + j] + b_hh[2 * H + j];
            go += b_ih[3 * H + j] + b_hh[3 * H + j];
            float iv = sigmoidf_(gi);
            float fv = sigmoidf_(gf);
            float gv = tanhf(gg);
            float ov = sigmoidf_(go);
            float c_new = fv * c0[j] + iv * gv;
            g_hbuf[0][j] = ov * tanhf(c_new);
        }
    } else {
        const int bb = b - H;
        const int l  = 1 + (bb >> 11);
        const int j  = bb & (H - 1);
        const float* Wh = W_hh + (size_t)l * 4 * H * H;
        const float* bi = b_ih + l * 4 * H;
        const float* bh = b_hh + l * 4 * H;
        const float4* __restrict__ h4 = (const float4*)(h0 + l * H);

        const float4* __restrict__ r0 = (const float4*)(Wh + (size_t)(0 * H + j) * H);
        const float4* __restrict__ r1 = (const float4*)(Wh + (size_t)(1 * H + j) * H);
        const float4* __restrict__ r2 = (const float4*)(Wh + (size_t)(2 * H + j) * H);
        const float4* __restrict__ r3 = (const float4*)(Wh + (size_t)(3 * H + j) * H);

        float a0 = 0.f, a1 = 0.f, a2 = 0.f, a3 = 0.f;
        #pragma unroll
        for (int k = t; k < H / 4; k += TPB) {
            float4 hv = h4[k];
            a0 += dot4(ld_stream(&r0[k]), hv);
            a1 += dot4(ld_stream(&r1[k]), hv);
            a2 += dot4(ld_stream(&r2[k]), hv);
            a3 += dot4(ld_stream(&r3[k]), hv);
        }
        #pragma unroll
        for (int off = 16; off > 0; off >>= 1) {
            a0 += __shfl_xor_sync(0xffffffffu, a0, off);
            a1 += __shfl_xor_sync(0xffffffffu, a1, off);
            a2 += __shfl_xor_sync(0xffffffffu, a2, off);
            a3 += __shfl_xor_sync(0xffffffffu, a3, off);
        }
        if (lane == 0) { s[0][warp] = a0; s[1][warp] = a1; s[2][warp] = a2; s[3][warp] = a3; }
        __syncthreads();
        if (t == 0) {
            float p0 = 0.f, p1 = 0.f, p2 = 0.f, p3 = 0.f;
            #pragma unroll
            for (int w = 0; w < NWARP; w++) {
                p0 += s[0][w]; p1 += s[1][w]; p2 += s[2][w]; p3 += s[3][w];
            }
            g_P[l - 1][0][j] = p0 + bi[0 * H + j] + bh[0 * H + j];
            g_P[l - 1][1][j] = p1 + bi[1 * H + j] + bh[1 * H + j];
            g_P[l - 1][2][j] = p2 + bi[2 * H + j] + bh[2 * H + j];
            g_P[l - 1][3][j] = p3 + bi[3 * H + j] + bh[3 * H + j];
        }
    }
}

// ---------------------------------------------------------------------------
// K2: layer-1 Wi GEMV (R5 structure; weights evict-first streamed).
// ---------------------------------------------------------------------------
__global__ void __launch_bounds__(TPB, 8) lstm_wi_stream(
    const float* __restrict__ Wi,
    const float* __restrict__ xin,
    const float* __restrict__ cin,
    const float* __restrict__ P,
    float* __restrict__ hout)
{
    const int j    = blockIdx.x;
    const int t    = threadIdx.x;
    const int warp = t >> 5;
    const int lane = t & 31;

    const float4* __restrict__ x4 = (const float4*)xin;
    const float4* __restrict__ r0 = (const float4*)(Wi + (size_t)(0 * H + j) * H);
    const float4* __restrict__ r1 = (const float4*)(Wi + (size_t)(1 * H + j) * H);
    const float4* __restrict__ r2 = (const float4*)(Wi + (size_t)(2 * H + j) * H);
    const float4* __restrict__ r3 = (const float4*)(Wi + (size_t)(3 * H + j) * H);

    float a0 = 0.f, a1 = 0.f, a2 = 0.f, a3 = 0.f;
    #pragma unroll
    for (int k = t; k < H / 4; k += TPB) {
        float4 xv = x4[k];
        a0 += dot4(ld_stream(&r0[k]), xv);
        a1 += dot4(ld_stream(&r1[k]), xv);
        a2 += dot4(ld_stream(&r2[k]), xv);
        a3 += dot4(ld_stream(&r3[k]), xv);
    }
    #pragma unroll
    for (int off = 16; off > 0; off >>= 1) {
        a0 += __shfl_xor_sync(0xffffffffu, a0, off);
        a1 += __shfl_xor_sync(0xffffffffu, a1, off);
        a2 += __shfl_xor_sync(0xffffffffu, a2, off);
        a3 += __shfl_xor_sync(0xffffffffu, a3, off);
    }
    __shared__ float s[4][NWARP];
    if (lane == 0) { s[0][warp] = a0; s[1][warp] = a1; s[2][warp] = a2; s[3][warp] = a3; }
    __syncthreads();
    if (t == 0) {
        float gi = 0.f, gf = 0.f, gg = 0.f, go = 0.f;
        #pragma unroll
        for (int w = 0; w < NWARP; w++) {
            gi += s[0][w]; gf += s[1][w]; gg += s[2][w]; go += s[3][w];
        }
        gi += P[0 * H + j];
        gf += P[1 * H + j];
        gg += P[2 * H + j];
        go += P[3 * H + j];
        float iv = sigmoidf_(gi);
        float fv = sigmoidf_(gf);
        float gv = tanhf(gg);
        float ov = sigmoidf_(go);
        float c_new = fv * cin[j] + iv * gv;
        hout[j] = ov * tanhf(c_new);
    }
}

// ---------------------------------------------------------------------------
// K3: layer-2 Wi GEMV — weights via 32-byte L2::evict_last loads so the 67MB
// Wi_2 set persists in L2 across graph replays (L2 not flushed per launch).
// Each thread covers one 32-byte chunk per row: 256 threads x 32B = 8KB row.
// ---------------------------------------------------------------------------
__global__ void __launch_bounds__(TPB, 8) lstm_wi_keep(
    const float* __restrict__ Wi,
    const float* __restrict__ xin,
    const float* __restrict__ cin,
    const float* __restrict__ P,
    float* __restrict__ hout)
{
    const int j    = blockIdx.x;
    const int t    = threadIdx.x;
    const int warp = t >> 5;
    const int lane = t & 31;

    const float4* __restrict__ x4 = (const float4*)xin;
    // x values for this thread's 32-byte chunk: float4s at indices 2t, 2t+1.
    const float4 xvA = x4[2 * t];
    const float4 xvB = x4[2 * t + 1];

    const float* r0 = Wi + (size_t)(0 * H + j) * H + 8 * t;
    const float* r1 = Wi + (size_t)(1 * H + j) * H + 8 * t;
    const float* r2 = Wi + (size_t)(2 * H + j) * H + 8 * t;
    const float* r3 = Wi + (size_t)(3 * H + j) * H + 8 * t;

    float4 wa, wb;
    ld_keep8(r0, wa, wb);
    float a0 = dot4(wa, xvA) + dot4(wb, xvB);
    ld_keep8(r1, wa, wb);
    float a1 = dot4(wa, xvA) + dot4(wb, xvB);
    ld_keep8(r2, wa, wb);
    float a2 = dot4(wa, xvA) + dot4(wb, xvB);
    ld_keep8(r3, wa, wb);
    float a3 = dot4(wa, xvA) + dot4(wb, xvB);

    #pragma unroll
    for (int off = 16; off > 0; off >>= 1) {
        a0 += __shfl_xor_sync(0xffffffffu, a0, off);
        a1 += __shfl_xor_sync(0xffffffffu, a1, off);
        a2 += __shfl_xor_sync(0xffffffffu, a2, off);
        a3 += __shfl_xor_sync(0xffffffffu, a3, off);
    }
    __shared__ float s[4][NWARP];
    if (lane == 0) { s[0][warp] = a0; s[1][warp] = a1; s[2][warp] = a2; s[3][warp] = a3; }
    __syncthreads();
    if (t == 0) {
        float gi = 0.f, gf = 0.f, gg = 0.f, go = 0.f;
        #pragma unroll
        for (int w = 0; w < NWARP; w++) {
            gi += s[0][w]; gf += s[1][w]; gg += s[2][w]; go += s[3][w];
        }
        gi += P[0 * H + j];
        gf += P[1 * H + j];
        gg += P[2 * H + j];
        go += P[3 * H + j];
        float iv = sigmoidf_(gi);
        float fv = sigmoidf_(gf);
        float gv = tanhf(gg);
        float ov = sigmoidf_(go);
        float c_new = fv * cin[j] + iv * gv;
        hout[j] = ov * tanhf(c_new);
    }
}

extern "C" void kernel_launch(void* const* d_in, const int* in_sizes, int n_in,
                              void* d_out, int out_size) {
    (void)in_sizes; (void)n_in; (void)out_size;
    const float* x    = (const float*)d_in[0];
    const float* W_ih = (const float*)d_in[1];
    const float* W_hh = (const float*)d_in[2];
    const float* b_ih = (const float*)d_in[3];
    const float* b_hh = (const float*)d_in[4];
    const float* h0   = (const float*)d_in[5];
    const float* c0   = (const float*)d_in[6];
    float* out = (float*)d_out;

    float* hbuf;
    cudaGetSymbolAddress((void**)&hbuf, g_hbuf);
    float* P;
    cudaGetSymbolAddress((void**)&P, g_P);

    const size_t Wstride = (size_t)4 * H * H;

    // K1: all input-parallel work (268 MB streamed evict-first)
    lstm_k1<<<3 * H, TPB>>>(x, W_ih, W_hh, b_ih, b_hh, h0, c0);
    // K2: layer 1 = Wi_1 @ h1 + P_1 -> h2 (streamed)
    lstm_wi_stream<<<H, TPB>>>(W_ih + Wstride, hbuf, c0 + H,
                               P, hbuf + H);
    // K3: layer 2 = Wi_2 @ h2 + P_2 -> out (L2-resident weights)
    lstm_wi_keep<<<H, TPB>>>(W_ih + 2 * Wstride, hbuf + H, c0 + 2 * H,
                             P + 4 * H, out);
}